// round 15
// baseline (speedup 1.0000x reference)
#include <cuda_runtime.h>
#include <math.h>

#define EMAX 1280
#define NMAX 384
#define TPB  256
#define NBLK 5       // one cluster of 5 CTAs; 5*256 = 1280 = one thread per edge

// ---------------- persistent device scratch ----------------------------------
__device__ int    g_snd[EMAX];
__device__ int    g_rcv[EMAX];
__device__ __align__(16) float g_h [NMAX * 8];   // [h0,h1,x0,x1,x2,0,0,0]
__device__ __align__(16) float g_ts[NMAX * 8];   // sender   [c0,c1,s1,c2,s2,c3,c4,s4]
__device__ __align__(16) float g_tr[NMAX * 8];   // receiver [c5,c6,c7,s7,c8,c9,s9,0]
__device__ __align__(16) float g_mi[2][NMAX * 8];
__device__ __align__(16) float g_mo[2][NMAX * 8];
__device__ float2 g_z1314[NMAX];
__device__ float2 g_ecs[9];
__device__ float2 g_ncs[11];

// ---------------- helpers -----------------------------------------------------
__device__ __forceinline__ void rot(float& z, float& x, float ct, float st) {
    float zn = z * ct - x * st;
    x = x * ct + z * st;
    z = zn;
}

// cluster-wide barrier (atomics published before arrive)
__device__ __forceinline__ void cluster_bar() {
    __threadfence();
    asm volatile("barrier.cluster.arrive.aligned;" ::: "memory");
    asm volatile("barrier.cluster.wait.aligned;" ::: "memory");
}

// ---------------- prep (wide): extract, H0, tables, constants ----------------
__global__ void prep_kernel(const float* __restrict__ X, const float* __restrict__ Ri,
                            const float* __restrict__ Ro, const float* __restrict__ W,
                            const float* __restrict__ te, const float* __restrict__ tn,
                            int N, int E) {
    int t = blockIdx.x * blockDim.x + threadIdx.x;
    int quarter = (N * E) >> 2;
    if (t < quarter) {
        float4 v = ((const float4*)Ro)[t];
        int base = t * 4;
        if (v.x > 0.5f) g_snd[ base      % E] =  base      / E;
        if (v.y > 0.5f) g_snd[(base + 1) % E] = (base + 1) / E;
        if (v.z > 0.5f) g_snd[(base + 2) % E] = (base + 2) / E;
        if (v.w > 0.5f) g_snd[(base + 3) % E] = (base + 3) / E;
    } else if (t < 2 * quarter) {
        int u = t - quarter;
        float4 v = ((const float4*)Ri)[u];
        int base = u * 4;
        if (v.x > 0.5f) g_rcv[ base      % E] =  base      / E;
        if (v.y > 0.5f) g_rcv[(base + 1) % E] = (base + 1) / E;
        if (v.z > 0.5f) g_rcv[(base + 2) % E] = (base + 2) / E;
        if (v.w > 0.5f) g_rcv[(base + 3) % E] = (base + 3) / E;
    }
    if (t < NMAX * 8) {
        g_mi[0][t] = 0.f; g_mi[1][t] = 0.f;
        g_mo[0][t] = 0.f; g_mo[1][t] = 0.f;
    }
    if (t < N) {
        float x0 = X[t * 3 + 0], x1 = X[t * 3 + 1], x2 = X[t * 3 + 2];
        float z0 = x0 * W[0] + x1 * W[2] + x2 * W[4];
        float z1 = x0 * W[1] + x1 * W[3] + x2 * W[5];
        const float TWOPI = 6.283185307179586f;
        float hv[5];
        hv[0] = TWOPI / (1.f + __expf(-z0));
        hv[1] = TWOPI / (1.f + __expf(-z1));
        hv[2] = x0; hv[3] = x1; hv[4] = x2;
#pragma unroll
        for (int j = 0; j < 5; j++) g_h[t * 8 + j] = hv[j];
        g_h[t * 8 + 5] = 0.f; g_h[t * 8 + 6] = 0.f; g_h[t * 8 + 7] = 0.f;
        float c[5], s[5];
#pragma unroll
        for (int j = 0; j < 5; j++) sincosf(hv[j] + te[j], &s[j], &c[j]);
        g_ts[t * 8 + 0] = c[0];
        g_ts[t * 8 + 1] = c[1];  g_ts[t * 8 + 2] = s[1];
        g_ts[t * 8 + 3] = c[2];  g_ts[t * 8 + 4] = s[2];
        g_ts[t * 8 + 5] = c[3];
        g_ts[t * 8 + 6] = c[4];  g_ts[t * 8 + 7] = s[4];
#pragma unroll
        for (int j = 0; j < 5; j++) sincosf(hv[j] + te[5 + j], &s[j], &c[j]);
        g_tr[t * 8 + 0] = c[0];
        g_tr[t * 8 + 1] = c[1];
        g_tr[t * 8 + 2] = c[2];  g_tr[t * 8 + 3] = s[2];
        g_tr[t * 8 + 4] = c[3];
        g_tr[t * 8 + 5] = c[4];  g_tr[t * 8 + 6] = s[4];
        g_tr[t * 8 + 7] = 0.f;
        g_z1314[t] = make_float2(cosf(x1 + tn[13] + tn[18] + tn[22]),
                                 cosf(x2 + tn[14] + tn[19] + tn[28]));
    }
    if (t >= 3072 && t < 3081) {
        int i = t - 3072;
        float ss, cc; sincosf(te[10 + i], &ss, &cc);
        g_ecs[i] = make_float2(cc, ss);
    }
    if (t >= 3104 && t < 3115) {
        int i = t - 3104; float ang = 0.f;
        switch (i) {
            case 0:  ang = tn[16]; break;
            case 1:  ang = tn[19]; break;
            case 2:  ang = tn[14]; break;
            case 3:  ang = tn[15]; break;
            case 4:  ang = tn[20]; break;
            case 5:  ang = tn[23] + tn[26]; break;
            case 6:  ang = tn[29]; break;
            case 7:  ang = 0.5f * tn[25]; break;
            case 8:  ang = tn[17] + tn[21]; break;
            case 9:  ang = tn[24] + tn[27]; break;
            case 10: ang = tn[30]; break;
        }
        float ss, cc; sincosf(ang, &ss, &cc);
        g_ncs[i] = make_float2(cc, ss);
    }
}

// ---------------- fused cluster kernel: per-CTA smem replicas ----------------
// Edge phase: own-smem tables (LDS), L2 atomics for messages only.
// Node phase: replicated in every CTA (<=2 nodes/thread) from L2 messages,
// updating the CTA's own smem replica. One cluster barrier per iteration.
__global__ void __launch_bounds__(TPB) __cluster_dims__(NBLK, 1, 1)
gnn_fused(const float* __restrict__ te, const float* __restrict__ tn,
          float* __restrict__ out, int N, int E) {
    __shared__ __align__(16) float s_ts[NMAX * 8];
    __shared__ __align__(16) float s_tr[NMAX * 8];
    __shared__ __align__(16) float s_h [NMAX * 8];
    int t = threadIdx.x;
    int tid = blockIdx.x * TPB + t;              // one edge per thread
    int sn = g_snd[tid], rc = g_rcv[tid];

    // stage replica into own smem
    for (int i = t; i < NMAX * 8; i += TPB) {
        s_ts[i] = g_ts[i];
        s_tr[i] = g_tr[i];
        s_h[i]  = g_h[i];
    }

    float2 T[9];
#pragma unroll
    for (int j = 0; j < 9; j++) T[j] = g_ecs[j];
    float2 NC[11];
#pragma unroll
    for (int j = 0; j < 11; j++) NC[j] = g_ncs[j];
    float te0 = te[0], te1 = te[1], te5 = te[5], te6 = te[6];
    float tn0 = tn[0], tn1 = tn[1], tn2 = tn[2], tn3 = tn[3], tn4 = tn[4];
    float tn5 = tn[5], tn6 = tn[6], tn7 = tn[7], tn10 = tn[10], tn11 = tn[11];
    float t15h = 0.5f * tn[15];

    // node ownership within this CTA's replica: n0 = t, n1 = t + TPB (if < N)
    int n0 = t, n1 = t + TPB;
    bool has1 = n1 < N;                           // n0 < 256 < N always
    float2 zz0 = g_z1314[n0];
    float2 zz1 = has1 ? g_z1314[n1] : make_float2(0.f, 0.f);
    __syncthreads();

    // node circuit: (f0..f7, h0, h1, zc13, zc14) -> new (h0, h1)
    auto node_circ = [&](float f0, float f1, float f2, float f3, float f4,
                         float f5, float f6, float f7,
                         float h0, float h1, float zc13, float zc14,
                         float& o0, float& o1) {
        float2 R;
        // ---- component B: <Z10> ----
        float cA10, sA10; __sincosf(h0 + tn10, &sA10, &cA10);
        float z11 = __cosf(h1 + tn11);
        float zb = cA10 * z11, xb = sA10;
        R = NC[8];  rot(zb, xb, R.x, R.y);
        zb *= zc13;
        R = NC[9];  rot(zb, xb, R.x, R.y);
        zb *= zc14;
        R = NC[10]; rot(zb, xb, R.x, R.y);
        float zB = zb;
        // ---- component A: <Z5>, 2-branch dephasing of q1 ----
        float a0 = 0.5f * (f0 + tn0);
        float a1 = 0.5f * (f1 + tn1);
        float cg0, sg0; __sincosf(t15h + a1, &sg0, &cg0);
        float cd, sd;   __sincosf(t15h - a1, &sd, &cd);
        float cg1 = -sd, sg1 = cd;
        float ca0, sa0; __sincosf(a0, &sa0, &ca0);
        float2 R25 = NC[7];
        float w[2], zw[2];
        {
            float p0 = ca0 * cg0, p1 = sa0 * cg1;
            float q0 = p0 * R25.x - p1 * R25.y, q1 = p1 * R25.x + p0 * R25.y;
            w[0] = q0 * q0 + q1 * q1;  zw[0] = q0 * q0 - q1 * q1;
            p0 = ca0 * sg0;  p1 = sa0 * sg1;
            q0 = p0 * R25.x - p1 * R25.y;  q1 = p1 * R25.x + p0 * R25.y;
            w[1] = q0 * q0 + q1 * q1;  zw[1] = q0 * q0 - q1 * q1;
        }
        float cA2v, sA2v; __sincosf(f2 + tn2, &sA2v, &cA2v);
        float z3 = __cosf(f3 + tn3);
        float z2 = cA2v * z3, x2 = sA2v;
        R = NC[0]; rot(z2, x2, R.x, R.y);
        float2 R19 = NC[1];
        float z2b0 =  z2, x2b0 = x2; rot(z2b0, x2b0, R19.x, R19.y);
        float z2b1 = -z2, x2b1 = x2; rot(z2b1, x2b1, R19.x, R19.y);
        float cA6v, sA6v; __sincosf(f6 + tn6, &sA6v, &cA6v);
        float z7c = __cosf(f7 + tn7);
        float z6 = cA6v * z7c, x6 = sA6v;
        R = NC[3]; rot(z6, x6, R.x, R.y);
        float cA5v, sA5v; __sincosf(f5 + tn5, &sA5v, &cA5v);
        float z4c = __cosf(f4 + tn4);
        float z5 = cA5v * z4c, x5 = sA5v;
        R = NC[2]; rot(z5, x5, R.x, R.y);
        z5 *= z6;
        R = NC[4]; rot(z5, x5, R.x, R.y);
        float2 R2326 = NC[5], R29 = NC[6];
        float zA = 0.f;
#pragma unroll
        for (int bsel = 0; bsel < 2; bsel++) {
            float z = z5 * (bsel ? z2b1 : z2b0), x = x5;
            rot(z, x, R2326.x, R2326.y);
            float zp = z * zw[bsel], xp = x * w[bsel];
            zA += zp * R29.x - xp * R29.y;
        }
        const float PI_F = 3.14159265358979f;
        o0 = PI_F * (1.f - zA);
        o1 = PI_F * (1.f - zB);
    };

    // update one node's row in the local replica
    auto node_update = [&](int n, float2 zz, int it) {
        float4 a  = __ldcg((const float4*)&g_mi[it][n * 8]);
        float  a4 = __ldcg(&g_mi[it][n * 8 + 4]);
        float4 bb = __ldcg((const float4*)&g_mo[it][n * 8]);
        float h0 = s_h[n * 8 + 0], h1 = s_h[n * 8 + 1];
        float o0, o1;
        node_circ(a.x, a.y, a.z, a.w, a4, bb.x, bb.y, bb.z,
                  h0, h1, zz.x, zz.y, o0, o1);
        s_h[n * 8 + 0] = o0;
        s_h[n * 8 + 1] = o1;
        float ss, cc;
        __sincosf(o0 + te0, &ss, &cc); s_ts[n * 8 + 0] = cc;
        __sincosf(o1 + te1, &ss, &cc); s_ts[n * 8 + 1] = cc; s_ts[n * 8 + 2] = ss;
        s_tr[n * 8 + 0] = __cosf(o0 + te5);
        s_tr[n * 8 + 1] = __cosf(o1 + te6);
    };

    for (int it = 0; it < 3; it++) {
        // ================= edge phase: own-smem tables, L2 message atomics ==
        {
            float4 tsa = *(const float4*)&s_ts[sn * 8];
            float4 tsb = *(const float4*)&s_ts[sn * 8 + 4];
            float4 tra = *(const float4*)&s_tr[rc * 8];
            float4 trb = *(const float4*)&s_tr[rc * 8 + 4];
            float4 hs  = *(const float4*)&s_h[sn * 8];
            float  hs4 = s_h[sn * 8 + 4];
            float4 hr  = *(const float4*)&s_h[rc * 8];

            float c0 = tsa.x, c1 = tsa.y, s1v = tsa.z, c2 = tsa.w;
            float s2v = tsb.x, c3 = tsb.y, c4 = tsb.z, s4v = tsb.w;
            float c5 = tra.x, c6 = tra.y, c7 = tra.z, s7v = tra.w;
            float c8 = trb.x, c9 = trb.y, s9v = trb.z;

            float z1 = c1 * c0, x1 = s1v; rot(z1, x1, T[0].x, T[0].y);
            float z2 = c2 * c3, x2 = s2v; rot(z2, x2, T[1].x, T[1].y);
            z2 *= z1;                     rot(z2, x2, T[4].x, T[4].y);
            float z4 = c4 * c5, x4 = s4v; rot(z4, x4, T[5].x, T[5].y);
            z4 *= z2;                     rot(z4, x4, T[6].x, T[6].y);
            float z9 = c9 * c8, x9 = s9v; rot(z9, x9, T[3].x, T[3].y);
            float z7 = c7 * c6, x7 = s7v; rot(z7, x7, T[2].x, T[2].y);
            z7 *= z9;                     rot(z7, x7, T[7].x, T[7].y);
            z7 *= z4;                     rot(z7, x7, T[8].x, T[8].y);

            float e = 0.5f * (1.0f - z7);
            if (it < 2) {
                float* mi = g_mi[it];
                float* mo = g_mo[it];
                atomicAdd(&mi[rc * 8 + 0], e * hs.x);
                atomicAdd(&mi[rc * 8 + 1], e * hs.y);
                atomicAdd(&mi[rc * 8 + 2], e * hs.z);
                atomicAdd(&mi[rc * 8 + 3], e * hs.w);
                atomicAdd(&mi[rc * 8 + 4], e * hs4);
                // node circuit never reads mo slots 3,4 (qubits 8,9 drop out)
                atomicAdd(&mo[sn * 8 + 0], e * hr.x);
                atomicAdd(&mo[sn * 8 + 1], e * hr.y);
                atomicAdd(&mo[sn * 8 + 2], e * hr.z);
            } else {
                out[tid] = e;
            }
        }
        if (it == 2) break;
        cluster_bar();                       // all CTAs' atomics visible

        // ================= node phase: replicated per CTA ===================
        node_update(n0, zz0, it);
        if (has1) node_update(n1, zz1, it);
        __syncthreads();                     // replica consistent for next edge
    }
}

// ---------------- launch (graph-capturable, 2 kernels) -----------------------
extern "C" void kernel_launch(void* const* d_in, const int* in_sizes, int n_in,
                              void* d_out, int out_size) {
    const float* X  = (const float*)d_in[0];
    const float* Ri = (const float*)d_in[1];
    const float* Ro = (const float*)d_in[2];
    const float* W  = (const float*)d_in[3];
    const float* te = (const float*)d_in[4];
    const float* tn = (const float*)d_in[5];
    int N = in_sizes[0] / 3;
    int E = in_sizes[1] / N;

    int pg = (2 * ((N * E) / 4) + 255) / 256;   // float4 scan of Ro + Ri
    prep_kernel<<<pg, 256>>>(X, Ri, Ro, W, te, tn, N, E);
    gnn_fused<<<NBLK, TPB>>>(te, tn, (float*)d_out, N, E);
}

// round 16
// speedup vs baseline: 1.0253x; 1.0253x over previous
#include <cuda_runtime.h>
#include <math.h>

#define EMAX 1280
#define NMAX 384
#define TPB  256

// ---------------- persistent device scratch ----------------------------------
__device__ int    g_snd[EMAX];
__device__ int    g_rcv[EMAX];
__device__ __align__(16) float g_h [NMAX * 8];   // [h0,h1,x0,x1,x2,0,0,0]
__device__ __align__(16) float g_ts[NMAX * 8];   // sender   [c0,c1,s1,c2,s2,c3,c4,s4]
__device__ __align__(16) float g_tr[NMAX * 8];   // receiver [c5,c6,c7,s7,c8,c9,s9,0]
__device__ __align__(16) float g_mi[2][NMAX * 8];
__device__ __align__(16) float g_mo[2][NMAX * 8];
__device__ float2 g_z1314[NMAX];
__device__ float2 g_ecs[9];
__device__ float2 g_ncs[11];

// ---------------- helpers -----------------------------------------------------
__device__ __forceinline__ void rot(float& z, float& x, float ct, float st) {
    float zn = z * ct - x * st;
    x = x * ct + z * st;
    z = zn;
}

struct NodeConst {
    float2 NC[11];
    float tn0, tn1, tn2, tn3, tn4, tn5, tn6, tn7, tn10, tn11, t15h;
    float te0, te1, te5, te6;
};

// closed-form node circuit: (f0..f7, h0, h1, z13, z14) -> (o0, o1)
__device__ __forceinline__ void node_circ(
    const NodeConst& P,
    float f0, float f1, float f2, float f3, float f4,
    float f5, float f6, float f7,
    float h0, float h1, float zc13, float zc14,
    float& o0, float& o1)
{
    float2 R;
    // component B: <Z10>
    float cA10, sA10; __sincosf(h0 + P.tn10, &sA10, &cA10);
    float z11 = __cosf(h1 + P.tn11);
    float zb = cA10 * z11, xb = sA10;
    R = P.NC[8];  rot(zb, xb, R.x, R.y);
    zb *= zc13;
    R = P.NC[9];  rot(zb, xb, R.x, R.y);
    zb *= zc14;
    R = P.NC[10]; rot(zb, xb, R.x, R.y);
    float zB = zb;
    // component A: <Z5>, 2-branch dephasing of q1
    float a0 = 0.5f * (f0 + P.tn0);
    float a1 = 0.5f * (f1 + P.tn1);
    float cg0, sg0; __sincosf(P.t15h + a1, &sg0, &cg0);
    float cd, sd;   __sincosf(P.t15h - a1, &sd, &cd);
    float cg1 = -sd, sg1 = cd;
    float ca0, sa0; __sincosf(a0, &sa0, &ca0);
    float2 R25 = P.NC[7];
    float w[2], zw[2];
    {
        float p0 = ca0 * cg0, p1 = sa0 * cg1;
        float q0 = p0 * R25.x - p1 * R25.y, q1 = p1 * R25.x + p0 * R25.y;
        w[0] = q0 * q0 + q1 * q1;  zw[0] = q0 * q0 - q1 * q1;
        p0 = ca0 * sg0;  p1 = sa0 * sg1;
        q0 = p0 * R25.x - p1 * R25.y;  q1 = p1 * R25.x + p0 * R25.y;
        w[1] = q0 * q0 + q1 * q1;  zw[1] = q0 * q0 - q1 * q1;
    }
    float cA2v, sA2v; __sincosf(f2 + P.tn2, &sA2v, &cA2v);
    float z3 = __cosf(f3 + P.tn3);
    float z2 = cA2v * z3, x2 = sA2v;
    R = P.NC[0]; rot(z2, x2, R.x, R.y);
    float2 R19 = P.NC[1];
    float z2b0 =  z2, x2b0 = x2; rot(z2b0, x2b0, R19.x, R19.y);
    float z2b1 = -z2, x2b1 = x2; rot(z2b1, x2b1, R19.x, R19.y);
    float cA6v, sA6v; __sincosf(f6 + P.tn6, &sA6v, &cA6v);
    float z7c = __cosf(f7 + P.tn7);
    float z6 = cA6v * z7c, x6 = sA6v;
    R = P.NC[3]; rot(z6, x6, R.x, R.y);
    float cA5v, sA5v; __sincosf(f5 + P.tn5, &sA5v, &cA5v);
    float z4c = __cosf(f4 + P.tn4);
    float z5 = cA5v * z4c, x5 = sA5v;
    R = P.NC[2]; rot(z5, x5, R.x, R.y);
    z5 *= z6;
    R = P.NC[4]; rot(z5, x5, R.x, R.y);
    float2 R2326 = P.NC[5], R29 = P.NC[6];
    float zA = 0.f;
#pragma unroll
    for (int bsel = 0; bsel < 2; bsel++) {
        float z = z5 * (bsel ? z2b1 : z2b0), x = x5;
        rot(z, x, R2326.x, R2326.y);
        float zp = z * zw[bsel], xp = x * w[bsel];
        zA += zp * R29.x - xp * R29.y;
    }
    const float PI_F = 3.14159265358979f;
    o0 = PI_F * (1.f - zA);
    o1 = PI_F * (1.f - zB);
}

__device__ __forceinline__ void load_node_const(NodeConst& P, const float* tn,
                                                const float* te) {
#pragma unroll
    for (int j = 0; j < 11; j++) P.NC[j] = g_ncs[j];
    P.tn0 = tn[0]; P.tn1 = tn[1]; P.tn2 = tn[2]; P.tn3 = tn[3]; P.tn4 = tn[4];
    P.tn5 = tn[5]; P.tn6 = tn[6]; P.tn7 = tn[7]; P.tn10 = tn[10]; P.tn11 = tn[11];
    P.t15h = 0.5f * tn[15];
    P.te0 = te[0]; P.te1 = te[1]; P.te5 = te[5]; P.te6 = te[6];
}

// recompute h^{t+1} for node n from message buffer `buf` and (h0,h1) at level t
__device__ __forceinline__ void recompute_h(const NodeConst& P, int n, int buf,
                                            float h0in, float h1in,
                                            float& o0, float& o1) {
    float4 a  = __ldcg((const float4*)&g_mi[buf][n * 8]);
    float  a4 = __ldcg(&g_mi[buf][n * 8 + 4]);
    float4 bb = __ldcg((const float4*)&g_mo[buf][n * 8]);
    float2 zz = g_z1314[n];
    node_circ(P, a.x, a.y, a.z, a.w, a4, bb.x, bb.y, bb.z,
              h0in, h1in, zz.x, zz.y, o0, o1);
}

// edge value from table-style components
__device__ __forceinline__ float edge_val(
    const float2* T,
    float c0, float c1, float s1v, float c2, float s2v, float c3, float c4, float s4v,
    float c5, float c6, float c7, float s7v, float c8, float c9, float s9v)
{
    float z1 = c1 * c0, x1 = s1v; rot(z1, x1, T[0].x, T[0].y);
    float z2 = c2 * c3, x2 = s2v; rot(z2, x2, T[1].x, T[1].y);
    z2 *= z1;                     rot(z2, x2, T[4].x, T[4].y);
    float z4 = c4 * c5, x4 = s4v; rot(z4, x4, T[5].x, T[5].y);
    z4 *= z2;                     rot(z4, x4, T[6].x, T[6].y);
    float z9 = c9 * c8, x9 = s9v; rot(z9, x9, T[3].x, T[3].y);
    float z7 = c7 * c6, x7 = s7v; rot(z7, x7, T[2].x, T[2].y);
    z7 *= z9;                     rot(z7, x7, T[7].x, T[7].y);
    z7 *= z4;                     rot(z7, x7, T[8].x, T[8].y);
    return 0.5f * (1.0f - z7);
}

// ---------------- K1: prep (wide) --------------------------------------------
__global__ void prep_kernel(const float* __restrict__ X, const float* __restrict__ Ri,
                            const float* __restrict__ Ro, const float* __restrict__ W,
                            const float* __restrict__ te, const float* __restrict__ tn,
                            int N, int E) {
    int t = blockIdx.x * blockDim.x + threadIdx.x;
    int quarter = (N * E) >> 2;
    if (t < quarter) {
        float4 v = ((const float4*)Ro)[t];
        int base = t * 4;
        if (v.x > 0.5f) g_snd[ base      % E] =  base      / E;
        if (v.y > 0.5f) g_snd[(base + 1) % E] = (base + 1) / E;
        if (v.z > 0.5f) g_snd[(base + 2) % E] = (base + 2) / E;
        if (v.w > 0.5f) g_snd[(base + 3) % E] = (base + 3) / E;
    } else if (t < 2 * quarter) {
        int u = t - quarter;
        float4 v = ((const float4*)Ri)[u];
        int base = u * 4;
        if (v.x > 0.5f) g_rcv[ base      % E] =  base      / E;
        if (v.y > 0.5f) g_rcv[(base + 1) % E] = (base + 1) / E;
        if (v.z > 0.5f) g_rcv[(base + 2) % E] = (base + 2) / E;
        if (v.w > 0.5f) g_rcv[(base + 3) % E] = (base + 3) / E;
    }
    if (t < NMAX * 8) {
        g_mi[0][t] = 0.f; g_mi[1][t] = 0.f;
        g_mo[0][t] = 0.f; g_mo[1][t] = 0.f;
    }
    if (t < N) {
        float x0 = X[t * 3 + 0], x1 = X[t * 3 + 1], x2 = X[t * 3 + 2];
        float z0 = x0 * W[0] + x1 * W[2] + x2 * W[4];
        float z1 = x0 * W[1] + x1 * W[3] + x2 * W[5];
        const float TWOPI = 6.283185307179586f;
        float hv[5];
        hv[0] = TWOPI / (1.f + __expf(-z0));
        hv[1] = TWOPI / (1.f + __expf(-z1));
        hv[2] = x0; hv[3] = x1; hv[4] = x2;
#pragma unroll
        for (int j = 0; j < 5; j++) g_h[t * 8 + j] = hv[j];
        g_h[t * 8 + 5] = 0.f; g_h[t * 8 + 6] = 0.f; g_h[t * 8 + 7] = 0.f;
        float c[5], s[5];
#pragma unroll
        for (int j = 0; j < 5; j++) sincosf(hv[j] + te[j], &s[j], &c[j]);
        g_ts[t * 8 + 0] = c[0];
        g_ts[t * 8 + 1] = c[1];  g_ts[t * 8 + 2] = s[1];
        g_ts[t * 8 + 3] = c[2];  g_ts[t * 8 + 4] = s[2];
        g_ts[t * 8 + 5] = c[3];
        g_ts[t * 8 + 6] = c[4];  g_ts[t * 8 + 7] = s[4];
#pragma unroll
        for (int j = 0; j < 5; j++) sincosf(hv[j] + te[5 + j], &s[j], &c[j]);
        g_tr[t * 8 + 0] = c[0];
        g_tr[t * 8 + 1] = c[1];
        g_tr[t * 8 + 2] = c[2];  g_tr[t * 8 + 3] = s[2];
        g_tr[t * 8 + 4] = c[3];
        g_tr[t * 8 + 5] = c[4];  g_tr[t * 8 + 6] = s[4];
        g_tr[t * 8 + 7] = 0.f;
        g_z1314[t] = make_float2(cosf(x1 + tn[13] + tn[18] + tn[22]),
                                 cosf(x2 + tn[14] + tn[19] + tn[28]));
    }
    if (t >= 3072 && t < 3081) {
        int i = t - 3072;
        float ss, cc; sincosf(te[10 + i], &ss, &cc);
        g_ecs[i] = make_float2(cc, ss);
    }
    if (t >= 3104 && t < 3115) {
        int i = t - 3104; float ang = 0.f;
        switch (i) {
            case 0:  ang = tn[16]; break;
            case 1:  ang = tn[19]; break;
            case 2:  ang = tn[14]; break;
            case 3:  ang = tn[15]; break;
            case 4:  ang = tn[20]; break;
            case 5:  ang = tn[23] + tn[26]; break;
            case 6:  ang = tn[29]; break;
            case 7:  ang = 0.5f * tn[25]; break;
            case 8:  ang = tn[17] + tn[21]; break;
            case 9:  ang = tn[24] + tn[27]; break;
            case 10: ang = tn[30]; break;
        }
        float ss, cc; sincosf(ang, &ss, &cc);
        g_ncs[i] = make_float2(cc, ss);
    }
}

// ---------------- K2: edge iteration 0 (tables valid) ------------------------
__global__ void __launch_bounds__(TPB) edge0_kernel(int E) {
    int k = blockIdx.x * TPB + threadIdx.x;
    if (k >= E) return;
    int sn = g_snd[k], rc = g_rcv[k];
    float2 T[9];
#pragma unroll
    for (int j = 0; j < 9; j++) T[j] = g_ecs[j];

    float4 tsa = __ldcg((const float4*)&g_ts[sn * 8]);
    float4 tsb = __ldcg((const float4*)&g_ts[sn * 8 + 4]);
    float4 tra = __ldcg((const float4*)&g_tr[rc * 8]);
    float4 trb = __ldcg((const float4*)&g_tr[rc * 8 + 4]);
    float4 hs  = __ldcg((const float4*)&g_h[sn * 8]);
    float  hs4 = __ldcg(&g_h[sn * 8 + 4]);
    float4 hr  = __ldcg((const float4*)&g_h[rc * 8]);

    float e = edge_val(T, tsa.x, tsa.y, tsa.z, tsa.w, tsb.x, tsb.y, tsb.z, tsb.w,
                       tra.x, tra.y, tra.z, tra.w, trb.x, trb.y, trb.z);
    atomicAdd(&g_mi[0][rc * 8 + 0], e * hs.x);
    atomicAdd(&g_mi[0][rc * 8 + 1], e * hs.y);
    atomicAdd(&g_mi[0][rc * 8 + 2], e * hs.z);
    atomicAdd(&g_mi[0][rc * 8 + 3], e * hs.w);
    atomicAdd(&g_mi[0][rc * 8 + 4], e * hs4);
    atomicAdd(&g_mo[0][sn * 8 + 0], e * hr.x);
    atomicAdd(&g_mo[0][sn * 8 + 1], e * hr.y);
    atomicAdd(&g_mo[0][sn * 8 + 2], e * hr.z);
}

// ---------------- K3: edge iteration 1 (redundant h1) ------------------------
__global__ void __launch_bounds__(TPB) edge1_kernel(
    const float* __restrict__ te, const float* __restrict__ tn, int E) {
    int k = blockIdx.x * TPB + threadIdx.x;
    if (k >= E) return;
    int sn = g_snd[k], rc = g_rcv[k];
    NodeConst P; load_node_const(P, tn, te);
    float2 T[9];
#pragma unroll
    for (int j = 0; j < 9; j++) T[j] = g_ecs[j];

    float4 hs = __ldcg((const float4*)&g_h[sn * 8]);   // h0_0,h0_1,x0,x1
    float  hx2s = __ldcg(&g_h[sn * 8 + 4]);
    float4 hr = __ldcg((const float4*)&g_h[rc * 8]);
    float4 tsa = __ldcg((const float4*)&g_ts[sn * 8]);  // [.,.,.,c2]
    float4 tsb = __ldcg((const float4*)&g_ts[sn * 8 + 4]); // [s2,c3,c4,s4]
    float4 tra = __ldcg((const float4*)&g_tr[rc * 8]);  // [.,.,c7,s7]
    float4 trb = __ldcg((const float4*)&g_tr[rc * 8 + 4]); // [c8,c9,s9,0]

    float h1s0, h1s1, h1r0, h1r1;
    recompute_h(P, sn, 0, hs.x, hs.y, h1s0, h1s1);
    recompute_h(P, rc, 0, hr.x, hr.y, h1r0, h1r1);

    // fresh angle components for changed features (slots 0,1)
    float c0 = __cosf(h1s0 + P.te0);
    float c1, s1v; __sincosf(h1s1 + P.te1, &s1v, &c1);
    float c5 = __cosf(h1r0 + P.te5);
    float c6 = __cosf(h1r1 + P.te6);

    float e = edge_val(T, c0, c1, s1v, tsa.w, tsb.x, tsb.y, tsb.z, tsb.w,
                       c5, c6, tra.z, tra.w, trb.x, trb.y, trb.z);
    atomicAdd(&g_mi[1][rc * 8 + 0], e * h1s0);
    atomicAdd(&g_mi[1][rc * 8 + 1], e * h1s1);
    atomicAdd(&g_mi[1][rc * 8 + 2], e * hs.z);
    atomicAdd(&g_mi[1][rc * 8 + 3], e * hs.w);
    atomicAdd(&g_mi[1][rc * 8 + 4], e * hx2s);
    atomicAdd(&g_mo[1][sn * 8 + 0], e * h1r0);
    atomicAdd(&g_mo[1][sn * 8 + 1], e * h1r1);
    atomicAdd(&g_mo[1][sn * 8 + 2], e * hr.z);
}

// ---------------- K4: edge iteration 2 -> out --------------------------------
__global__ void __launch_bounds__(TPB) edge2_kernel(
    const float* __restrict__ te, const float* __restrict__ tn,
    float* __restrict__ out, int E) {
    int k = blockIdx.x * TPB + threadIdx.x;
    if (k >= E) return;
    int sn = g_snd[k], rc = g_rcv[k];
    NodeConst P; load_node_const(P, tn, te);
    float2 T[9];
#pragma unroll
    for (int j = 0; j < 9; j++) T[j] = g_ecs[j];

    float4 hs = __ldcg((const float4*)&g_h[sn * 8]);
    float4 hr = __ldcg((const float4*)&g_h[rc * 8]);
    float4 tsa = __ldcg((const float4*)&g_ts[sn * 8]);
    float4 tsb = __ldcg((const float4*)&g_ts[sn * 8 + 4]);
    float4 tra = __ldcg((const float4*)&g_tr[rc * 8]);
    float4 trb = __ldcg((const float4*)&g_tr[rc * 8 + 4]);

    // recompute h1 (bit-identical to K3's), then h2 from iter-1 messages
    float h1s0, h1s1, h1r0, h1r1;
    recompute_h(P, sn, 0, hs.x, hs.y, h1s0, h1s1);
    recompute_h(P, rc, 0, hr.x, hr.y, h1r0, h1r1);
    float h2s0, h2s1, h2r0, h2r1;
    recompute_h(P, sn, 1, h1s0, h1s1, h2s0, h2s1);
    recompute_h(P, rc, 1, h1r0, h1r1, h2r0, h2r1);

    float c0 = __cosf(h2s0 + P.te0);
    float c1, s1v; __sincosf(h2s1 + P.te1, &s1v, &c1);
    float c5 = __cosf(h2r0 + P.te5);
    float c6 = __cosf(h2r1 + P.te6);

    out[k] = edge_val(T, c0, c1, s1v, tsa.w, tsb.x, tsb.y, tsb.z, tsb.w,
                      c5, c6, tra.z, tra.w, trb.x, trb.y, trb.z);
}

// ---------------- launch (graph-capturable, 4 kernels) -----------------------
extern "C" void kernel_launch(void* const* d_in, const int* in_sizes, int n_in,
                              void* d_out, int out_size) {
    const float* X  = (const float*)d_in[0];
    const float* Ri = (const float*)d_in[1];
    const float* Ro = (const float*)d_in[2];
    const float* W  = (const float*)d_in[3];
    const float* te = (const float*)d_in[4];
    const float* tn = (const float*)d_in[5];
    int N = in_sizes[0] / 3;
    int E = in_sizes[1] / N;

    int pg = (2 * ((N * E) / 4) + 255) / 256;   // float4 scan of Ro + Ri
    int eb = (E + TPB - 1) / TPB;               // 5 blocks, one thread per edge
    prep_kernel<<<pg, 256>>>(X, Ri, Ro, W, te, tn, N, E);
    edge0_kernel<<<eb, TPB>>>(E);
    edge1_kernel<<<eb, TPB>>>(te, tn, E);
    edge2_kernel<<<eb, TPB>>>(te, tn, (float*)d_out, E);
}

// round 17
// speedup vs baseline: 1.0555x; 1.0295x over previous
#include <cuda_runtime.h>
#include <math.h>

#define EMAX 1280
#define NMAX 384
#define TPB  256

// ---------------- persistent device scratch ----------------------------------
__device__ int    g_snd[EMAX];
__device__ int    g_rcv[EMAX];
__device__ __align__(16) float g_h [NMAX * 8];   // [h0,h1,x0,x1,x2,0,0,0]
__device__ __align__(16) float g_ts[NMAX * 8];   // sender   [c0,c1,s1,c2,s2,c3,c4,s4]
__device__ __align__(16) float g_tr[NMAX * 8];   // receiver [c5,c6,c7,s7,c8,c9,s9,0]
__device__ __align__(16) float g_mi[2][NMAX * 8];
__device__ __align__(16) float g_mo[2][NMAX * 8];
__device__ float2 g_h1[NMAX];      // h^1 per node (written redundantly in K3)
__device__ float2 g_z1314[NMAX];
__device__ float2 g_ecs[9];
__device__ float2 g_ncs[11];

// ---------------- helpers -----------------------------------------------------
__device__ __forceinline__ void rot(float& z, float& x, float ct, float st) {
    float zn = z * ct - x * st;
    x = x * ct + z * st;
    z = zn;
}

struct NodeConst {
    float2 NC[11];
    float tn0, tn1, tn2, tn3, tn4, tn5, tn6, tn7, tn10, tn11, t15h;
    float te0, te1, te5, te6;
};

// closed-form node circuit: (f0..f7, h0, h1, z13, z14) -> (o0, o1)
__device__ __forceinline__ void node_circ(
    const NodeConst& P,
    float f0, float f1, float f2, float f3, float f4,
    float f5, float f6, float f7,
    float h0, float h1, float zc13, float zc14,
    float& o0, float& o1)
{
    float2 R;
    // component B: <Z10>
    float cA10, sA10; __sincosf(h0 + P.tn10, &sA10, &cA10);
    float z11 = __cosf(h1 + P.tn11);
    float zb = cA10 * z11, xb = sA10;
    R = P.NC[8];  rot(zb, xb, R.x, R.y);
    zb *= zc13;
    R = P.NC[9];  rot(zb, xb, R.x, R.y);
    zb *= zc14;
    R = P.NC[10]; rot(zb, xb, R.x, R.y);
    float zB = zb;
    // component A: <Z5>, 2-branch dephasing of q1
    float a0 = 0.5f * (f0 + P.tn0);
    float a1 = 0.5f * (f1 + P.tn1);
    float cg0, sg0; __sincosf(P.t15h + a1, &sg0, &cg0);
    float cd, sd;   __sincosf(P.t15h - a1, &sd, &cd);
    float cg1 = -sd, sg1 = cd;
    float ca0, sa0; __sincosf(a0, &sa0, &ca0);
    float2 R25 = P.NC[7];
    float w[2], zw[2];
    {
        float p0 = ca0 * cg0, p1 = sa0 * cg1;
        float q0 = p0 * R25.x - p1 * R25.y, q1 = p1 * R25.x + p0 * R25.y;
        w[0] = q0 * q0 + q1 * q1;  zw[0] = q0 * q0 - q1 * q1;
        p0 = ca0 * sg0;  p1 = sa0 * sg1;
        q0 = p0 * R25.x - p1 * R25.y;  q1 = p1 * R25.x + p0 * R25.y;
        w[1] = q0 * q0 + q1 * q1;  zw[1] = q0 * q0 - q1 * q1;
    }
    float cA2v, sA2v; __sincosf(f2 + P.tn2, &sA2v, &cA2v);
    float z3 = __cosf(f3 + P.tn3);
    float z2 = cA2v * z3, x2 = sA2v;
    R = P.NC[0]; rot(z2, x2, R.x, R.y);
    float2 R19 = P.NC[1];
    float z2b0 =  z2, x2b0 = x2; rot(z2b0, x2b0, R19.x, R19.y);
    float z2b1 = -z2, x2b1 = x2; rot(z2b1, x2b1, R19.x, R19.y);
    float cA6v, sA6v; __sincosf(f6 + P.tn6, &sA6v, &cA6v);
    float z7c = __cosf(f7 + P.tn7);
    float z6 = cA6v * z7c, x6 = sA6v;
    R = P.NC[3]; rot(z6, x6, R.x, R.y);
    float cA5v, sA5v; __sincosf(f5 + P.tn5, &sA5v, &cA5v);
    float z4c = __cosf(f4 + P.tn4);
    float z5 = cA5v * z4c, x5 = sA5v;
    R = P.NC[2]; rot(z5, x5, R.x, R.y);
    z5 *= z6;
    R = P.NC[4]; rot(z5, x5, R.x, R.y);
    float2 R2326 = P.NC[5], R29 = P.NC[6];
    float zA = 0.f;
#pragma unroll
    for (int bsel = 0; bsel < 2; bsel++) {
        float z = z5 * (bsel ? z2b1 : z2b0), x = x5;
        rot(z, x, R2326.x, R2326.y);
        float zp = z * zw[bsel], xp = x * w[bsel];
        zA += zp * R29.x - xp * R29.y;
    }
    const float PI_F = 3.14159265358979f;
    o0 = PI_F * (1.f - zA);
    o1 = PI_F * (1.f - zB);
}

__device__ __forceinline__ void load_node_const(NodeConst& P, const float* tn,
                                                const float* te) {
#pragma unroll
    for (int j = 0; j < 11; j++) P.NC[j] = g_ncs[j];
    P.tn0 = tn[0]; P.tn1 = tn[1]; P.tn2 = tn[2]; P.tn3 = tn[3]; P.tn4 = tn[4];
    P.tn5 = tn[5]; P.tn6 = tn[6]; P.tn7 = tn[7]; P.tn10 = tn[10]; P.tn11 = tn[11];
    P.t15h = 0.5f * tn[15];
    P.te0 = te[0]; P.te1 = te[1]; P.te5 = te[5]; P.te6 = te[6];
}

// h^{t+1} for node n from message buffer `buf` and (h0,h1) at level t
__device__ __forceinline__ void recompute_h(const NodeConst& P, int n, int buf,
                                            float h0in, float h1in,
                                            float& o0, float& o1) {
    float4 a  = __ldcg((const float4*)&g_mi[buf][n * 8]);
    float  a4 = __ldcg(&g_mi[buf][n * 8 + 4]);
    float4 bb = __ldcg((const float4*)&g_mo[buf][n * 8]);
    float2 zz = g_z1314[n];
    node_circ(P, a.x, a.y, a.z, a.w, a4, bb.x, bb.y, bb.z,
              h0in, h1in, zz.x, zz.y, o0, o1);
}

// edge value from table-style components
__device__ __forceinline__ float edge_val(
    const float2* T,
    float c0, float c1, float s1v, float c2, float s2v, float c3, float c4, float s4v,
    float c5, float c6, float c7, float s7v, float c8, float c9, float s9v)
{
    float z1 = c1 * c0, x1 = s1v; rot(z1, x1, T[0].x, T[0].y);
    float z2 = c2 * c3, x2 = s2v; rot(z2, x2, T[1].x, T[1].y);
    z2 *= z1;                     rot(z2, x2, T[4].x, T[4].y);
    float z4 = c4 * c5, x4 = s4v; rot(z4, x4, T[5].x, T[5].y);
    z4 *= z2;                     rot(z4, x4, T[6].x, T[6].y);
    float z9 = c9 * c8, x9 = s9v; rot(z9, x9, T[3].x, T[3].y);
    float z7 = c7 * c6, x7 = s7v; rot(z7, x7, T[2].x, T[2].y);
    z7 *= z9;                     rot(z7, x7, T[7].x, T[7].y);
    z7 *= z4;                     rot(z7, x7, T[8].x, T[8].y);
    return 0.5f * (1.0f - z7);
}

// ---------------- K1: prep (wide) --------------------------------------------
__global__ void prep_kernel(const float* __restrict__ X, const float* __restrict__ Ri,
                            const float* __restrict__ Ro, const float* __restrict__ W,
                            const float* __restrict__ te, const float* __restrict__ tn,
                            int N, int E) {
    int t = blockIdx.x * blockDim.x + threadIdx.x;
    int quarter = (N * E) >> 2;
    if (t < quarter) {
        float4 v = ((const float4*)Ro)[t];
        int base = t * 4;
        if (v.x > 0.5f) g_snd[ base      % E] =  base      / E;
        if (v.y > 0.5f) g_snd[(base + 1) % E] = (base + 1) / E;
        if (v.z > 0.5f) g_snd[(base + 2) % E] = (base + 2) / E;
        if (v.w > 0.5f) g_snd[(base + 3) % E] = (base + 3) / E;
    } else if (t < 2 * quarter) {
        int u = t - quarter;
        float4 v = ((const float4*)Ri)[u];
        int base = u * 4;
        if (v.x > 0.5f) g_rcv[ base      % E] =  base      / E;
        if (v.y > 0.5f) g_rcv[(base + 1) % E] = (base + 1) / E;
        if (v.z > 0.5f) g_rcv[(base + 2) % E] = (base + 2) / E;
        if (v.w > 0.5f) g_rcv[(base + 3) % E] = (base + 3) / E;
    }
    if (t < NMAX * 8) {
        g_mi[0][t] = 0.f; g_mi[1][t] = 0.f;
        g_mo[0][t] = 0.f; g_mo[1][t] = 0.f;
    }
    if (t < N) {
        float x0 = X[t * 3 + 0], x1 = X[t * 3 + 1], x2 = X[t * 3 + 2];
        float z0 = x0 * W[0] + x1 * W[2] + x2 * W[4];
        float z1 = x0 * W[1] + x1 * W[3] + x2 * W[5];
        const float TWOPI = 6.283185307179586f;
        float hv[5];
        hv[0] = TWOPI / (1.f + __expf(-z0));
        hv[1] = TWOPI / (1.f + __expf(-z1));
        hv[2] = x0; hv[3] = x1; hv[4] = x2;
#pragma unroll
        for (int j = 0; j < 5; j++) g_h[t * 8 + j] = hv[j];
        g_h[t * 8 + 5] = 0.f; g_h[t * 8 + 6] = 0.f; g_h[t * 8 + 7] = 0.f;
        float c[5], s[5];
#pragma unroll
        for (int j = 0; j < 5; j++) sincosf(hv[j] + te[j], &s[j], &c[j]);
        g_ts[t * 8 + 0] = c[0];
        g_ts[t * 8 + 1] = c[1];  g_ts[t * 8 + 2] = s[1];
        g_ts[t * 8 + 3] = c[2];  g_ts[t * 8 + 4] = s[2];
        g_ts[t * 8 + 5] = c[3];
        g_ts[t * 8 + 6] = c[4];  g_ts[t * 8 + 7] = s[4];
#pragma unroll
        for (int j = 0; j < 5; j++) sincosf(hv[j] + te[5 + j], &s[j], &c[j]);
        g_tr[t * 8 + 0] = c[0];
        g_tr[t * 8 + 1] = c[1];
        g_tr[t * 8 + 2] = c[2];  g_tr[t * 8 + 3] = s[2];
        g_tr[t * 8 + 4] = c[3];
        g_tr[t * 8 + 5] = c[4];  g_tr[t * 8 + 6] = s[4];
        g_tr[t * 8 + 7] = 0.f;
        g_z1314[t] = make_float2(cosf(x1 + tn[13] + tn[18] + tn[22]),
                                 cosf(x2 + tn[14] + tn[19] + tn[28]));
    }
    if (t >= 3072 && t < 3081) {
        int i = t - 3072;
        float ss, cc; sincosf(te[10 + i], &ss, &cc);
        g_ecs[i] = make_float2(cc, ss);
    }
    if (t >= 3104 && t < 3115) {
        int i = t - 3104; float ang = 0.f;
        switch (i) {
            case 0:  ang = tn[16]; break;
            case 1:  ang = tn[19]; break;
            case 2:  ang = tn[14]; break;
            case 3:  ang = tn[15]; break;
            case 4:  ang = tn[20]; break;
            case 5:  ang = tn[23] + tn[26]; break;
            case 6:  ang = tn[29]; break;
            case 7:  ang = 0.5f * tn[25]; break;
            case 8:  ang = tn[17] + tn[21]; break;
            case 9:  ang = tn[24] + tn[27]; break;
            case 10: ang = tn[30]; break;
        }
        float ss, cc; sincosf(ang, &ss, &cc);
        g_ncs[i] = make_float2(cc, ss);
    }
}

// ---------------- K2: edge iteration 0 (tables valid) ------------------------
__global__ void __launch_bounds__(TPB) edge0_kernel(int E) {
    int k = blockIdx.x * TPB + threadIdx.x;
    if (k >= E) return;
    int sn = g_snd[k], rc = g_rcv[k];
    float2 T[9];
#pragma unroll
    for (int j = 0; j < 9; j++) T[j] = g_ecs[j];

    float4 tsa = __ldcg((const float4*)&g_ts[sn * 8]);
    float4 tsb = __ldcg((const float4*)&g_ts[sn * 8 + 4]);
    float4 tra = __ldcg((const float4*)&g_tr[rc * 8]);
    float4 trb = __ldcg((const float4*)&g_tr[rc * 8 + 4]);
    float4 hs  = __ldcg((const float4*)&g_h[sn * 8]);
    float  hs4 = __ldcg(&g_h[sn * 8 + 4]);
    float4 hr  = __ldcg((const float4*)&g_h[rc * 8]);

    float e = edge_val(T, tsa.x, tsa.y, tsa.z, tsa.w, tsb.x, tsb.y, tsb.z, tsb.w,
                       tra.x, tra.y, tra.z, tra.w, trb.x, trb.y, trb.z);
    atomicAdd(&g_mi[0][rc * 8 + 0], e * hs.x);
    atomicAdd(&g_mi[0][rc * 8 + 1], e * hs.y);
    atomicAdd(&g_mi[0][rc * 8 + 2], e * hs.z);
    atomicAdd(&g_mi[0][rc * 8 + 3], e * hs.w);
    atomicAdd(&g_mi[0][rc * 8 + 4], e * hs4);
    atomicAdd(&g_mo[0][sn * 8 + 0], e * hr.x);
    atomicAdd(&g_mo[0][sn * 8 + 1], e * hr.y);
    atomicAdd(&g_mo[0][sn * 8 + 2], e * hr.z);
}

// ---------------- K3: edge iteration 1 (computes + stores h1) ----------------
__global__ void __launch_bounds__(TPB) edge1_kernel(
    const float* __restrict__ te, const float* __restrict__ tn, int E) {
    int k = blockIdx.x * TPB + threadIdx.x;
    if (k >= E) return;
    int sn = g_snd[k], rc = g_rcv[k];
    NodeConst P; load_node_const(P, tn, te);
    float2 T[9];
#pragma unroll
    for (int j = 0; j < 9; j++) T[j] = g_ecs[j];

    float4 hs = __ldcg((const float4*)&g_h[sn * 8]);
    float  hx2s = __ldcg(&g_h[sn * 8 + 4]);
    float4 hr = __ldcg((const float4*)&g_h[rc * 8]);
    float4 tsa = __ldcg((const float4*)&g_ts[sn * 8]);
    float4 tsb = __ldcg((const float4*)&g_ts[sn * 8 + 4]);
    float4 tra = __ldcg((const float4*)&g_tr[rc * 8]);
    float4 trb = __ldcg((const float4*)&g_tr[rc * 8 + 4]);

    float h1s0, h1s1, h1r0, h1r1;
    recompute_h(P, sn, 0, hs.x, hs.y, h1s0, h1s1);
    recompute_h(P, rc, 0, hr.x, hr.y, h1r0, h1r1);

    // materialize h1 for K4 (redundant identical writes are benign)
    g_h1[sn] = make_float2(h1s0, h1s1);
    g_h1[rc] = make_float2(h1r0, h1r1);

    float c0 = __cosf(h1s0 + P.te0);
    float c1, s1v; __sincosf(h1s1 + P.te1, &s1v, &c1);
    float c5 = __cosf(h1r0 + P.te5);
    float c6 = __cosf(h1r1 + P.te6);

    float e = edge_val(T, c0, c1, s1v, tsa.w, tsb.x, tsb.y, tsb.z, tsb.w,
                       c5, c6, tra.z, tra.w, trb.x, trb.y, trb.z);
    atomicAdd(&g_mi[1][rc * 8 + 0], e * h1s0);
    atomicAdd(&g_mi[1][rc * 8 + 1], e * h1s1);
    atomicAdd(&g_mi[1][rc * 8 + 2], e * hs.z);
    atomicAdd(&g_mi[1][rc * 8 + 3], e * hs.w);
    atomicAdd(&g_mi[1][rc * 8 + 4], e * hx2s);
    atomicAdd(&g_mo[1][sn * 8 + 0], e * h1r0);
    atomicAdd(&g_mo[1][sn * 8 + 1], e * h1r1);
    atomicAdd(&g_mo[1][sn * 8 + 2], e * hr.z);
}

// ---------------- K4: edge iteration 2 (loads h1, one circuit stage) ---------
__global__ void __launch_bounds__(TPB) edge2_kernel(
    const float* __restrict__ te, const float* __restrict__ tn,
    float* __restrict__ out, int E) {
    int k = blockIdx.x * TPB + threadIdx.x;
    if (k >= E) return;
    int sn = g_snd[k], rc = g_rcv[k];
    NodeConst P; load_node_const(P, tn, te);
    float2 T[9];
#pragma unroll
    for (int j = 0; j < 9; j++) T[j] = g_ecs[j];

    // one parallel load volley: h1, residual tables (messages loaded in recompute_h)
    float2 h1s = __ldcg(&g_h1[sn]);
    float2 h1r = __ldcg(&g_h1[rc]);
    float4 tsa = __ldcg((const float4*)&g_ts[sn * 8]);
    float4 tsb = __ldcg((const float4*)&g_ts[sn * 8 + 4]);
    float4 tra = __ldcg((const float4*)&g_tr[rc * 8]);
    float4 trb = __ldcg((const float4*)&g_tr[rc * 8 + 4]);

    // single node_circ stage: h1 -> h2 (sn and rc independent, overlap)
    float h2s0, h2s1, h2r0, h2r1;
    recompute_h(P, sn, 1, h1s.x, h1s.y, h2s0, h2s1);
    recompute_h(P, rc, 1, h1r.x, h1r.y, h2r0, h2r1);

    float c0 = __cosf(h2s0 + P.te0);
    float c1, s1v; __sincosf(h2s1 + P.te1, &s1v, &c1);
    float c5 = __cosf(h2r0 + P.te5);
    float c6 = __cosf(h2r1 + P.te6);

    out[k] = edge_val(T, c0, c1, s1v, tsa.w, tsb.x, tsb.y, tsb.z, tsb.w,
                      c5, c6, tra.z, tra.w, trb.x, trb.y, trb.z);
}

// ---------------- launch (graph-capturable, 4 kernels) -----------------------
extern "C" void kernel_launch(void* const* d_in, const int* in_sizes, int n_in,
                              void* d_out, int out_size) {
    const float* X  = (const float*)d_in[0];
    const float* Ri = (const float*)d_in[1];
    const float* Ro = (const float*)d_in[2];
    const float* W  = (const float*)d_in[3];
    const float* te = (const float*)d_in[4];
    const float* tn = (const float*)d_in[5];
    int N = in_sizes[0] / 3;
    int E = in_sizes[1] / N;

    int pg = (2 * ((N * E) / 4) + 255) / 256;   // float4 scan of Ro + Ri
    int eb = (E + TPB - 1) / TPB;               // 5 blocks, one thread per edge
    prep_kernel<<<pg, 256>>>(X, Ri, Ro, W, te, tn, N, E);
    edge0_kernel<<<eb, TPB>>>(E);
    edge1_kernel<<<eb, TPB>>>(te, tn, E);
    edge2_kernel<<<eb, TPB>>>(te, tn, (float*)d_out, E);
}